// round 1
// baseline (speedup 1.0000x reference)
#include <cuda_runtime.h>
#include <math.h>
#include <stdint.h>

#define BB      8
#define NHEADS  8
#define HD      32
#define NN      1024
#define CDIM    256
#define TABLE_SZ 3969
#define CPBH    512

// ---------------- scratch (device globals; no allocation allowed) ------------
__device__ float g_qkv[BB * NN * 3 * CDIM];          // 24 MB  [b*N+n][768]
__device__ float g_qs [BB * NHEADS * NN * HD];       // 8 MB   [(b*H+h)*N+n][32]  (l2norm+qe)*scale
__device__ float g_kn [BB * NHEADS * NN * HD];       // 8 MB   l2norm(k)
__device__ float g_v  [BB * NHEADS * NN * HD];       // 8 MB
__device__ float g_tab[NHEADS * TABLE_SZ];           // 127 KB [h][t]
__device__ float g_ao [BB * NN * CDIM];              // 8 MB   [b*N+n][h*32+d]

// ---------------- CPB MLP: table_out[h][t] -----------------------------------
__global__ void cpb_kernel(const float* __restrict__ coords,
                           const float* __restrict__ fc1w, const float* __restrict__ fc1b,
                           const float* __restrict__ fc2w, const float* __restrict__ fc2b) {
    int t = blockIdx.x;
    float c0 = coords[t * 2 + 0];
    float c1 = coords[t * 2 + 1];
    float acc[NHEADS];
#pragma unroll
    for (int h = 0; h < NHEADS; h++) acc[h] = 0.f;
    for (int j = threadIdx.x; j < CPBH; j += blockDim.x) {
        float hv = fmaxf(c0 * fc1w[j * 2] + c1 * fc1w[j * 2 + 1] + fc1b[j], 0.f);
#pragma unroll
        for (int h = 0; h < NHEADS; h++) acc[h] += hv * fc2w[h * CPBH + j];
    }
    // block reduce (128 threads = 4 warps)
    __shared__ float red[4][NHEADS];
    int lane = threadIdx.x & 31, warp = threadIdx.x >> 5;
#pragma unroll
    for (int h = 0; h < NHEADS; h++)
        for (int o = 16; o; o >>= 1) acc[h] += __shfl_xor_sync(0xffffffffu, acc[h], o);
    if (lane == 0)
#pragma unroll
        for (int h = 0; h < NHEADS; h++) red[warp][h] = acc[h];
    __syncthreads();
    if (threadIdx.x < NHEADS) {
        float s = fc2b[threadIdx.x];
        for (int w = 0; w < 4; w++) s += red[w][threadIdx.x];
        g_tab[threadIdx.x * TABLE_SZ + t] = s;
    }
}

// ---------------- tiled fp32 GEMM: C[M][N] = A[M][K] @ W[N][K]^T + bias -------
// BM=BN=64, BK=32, 256 threads, 4x4 micro-tile
__global__ void gemm_bias_kernel(const float* __restrict__ A, const float* __restrict__ W,
                                 const float* __restrict__ bias, float* __restrict__ C,
                                 int M, int N, int K) {
    __shared__ float As[32][68];
    __shared__ float Ws[32][68];
    const int bm = blockIdx.y * 64, bn = blockIdx.x * 64;
    const int tid = threadIdx.x;
    const int tr = tid >> 4, tc = tid & 15;   // 16x16 thread grid
    float acc[4][4] = {};
    for (int k0 = 0; k0 < K; k0 += 32) {
#pragma unroll
        for (int i = 0; i < 8; i++) {
            int e = tid + i * 256;
            int m = e >> 5, k = e & 31;
            As[k][m] = A[(size_t)(bm + m) * K + k0 + k];
        }
#pragma unroll
        for (int i = 0; i < 8; i++) {
            int e = tid + i * 256;
            int n = e >> 5, k = e & 31;
            Ws[k][n] = W[(size_t)(bn + n) * K + k0 + k];
        }
        __syncthreads();
#pragma unroll
        for (int k = 0; k < 32; k++) {
            float a[4], b[4];
#pragma unroll
            for (int i = 0; i < 4; i++) a[i] = As[k][tr * 4 + i];
#pragma unroll
            for (int j = 0; j < 4; j++) b[j] = Ws[k][tc * 4 + j];
#pragma unroll
            for (int i = 0; i < 4; i++)
#pragma unroll
                for (int j = 0; j < 4; j++) acc[i][j] += a[i] * b[j];
        }
        __syncthreads();
    }
#pragma unroll
    for (int i = 0; i < 4; i++) {
        int m = bm + tr * 4 + i;
#pragma unroll
        for (int j = 0; j < 4; j++) {
            int n = bn + tc * 4 + j;
            C[(size_t)m * N + n] = acc[i][j] + bias[n];
        }
    }
}

// ---------------- prep: split qkv, l2norm q/k, apply query_embedding+scale ----
__global__ void prep_kernel(const float* __restrict__ qe, const float* __restrict__ temp) {
    int gtid = blockIdx.x * blockDim.x + threadIdx.x;
    int w = gtid >> 5;            // one warp per (b,h,n)
    int lane = gtid & 31;
    if (w >= BB * NHEADS * NN) return;
    int n = w % NN;
    int h = (w / NN) % NHEADS;
    int b = w / (NN * NHEADS);
    size_t row = (size_t)(b * NN + n) * (3 * CDIM);
    float q = g_qkv[row + h * HD + lane];
    float k = g_qkv[row + CDIM + h * HD + lane];
    float v = g_qkv[row + 2 * CDIM + h * HD + lane];
    float q2 = q * q, k2 = k * k;
#pragma unroll
    for (int o = 16; o; o >>= 1) {
        q2 += __shfl_xor_sync(0xffffffffu, q2, o);
        k2 += __shfl_xor_sync(0xffffffffu, k2, o);
    }
    float qn = q / fmaxf(sqrtf(q2), 1e-12f) + qe[h * HD + lane];
    float kn = k / fmaxf(sqrtf(k2), 1e-12f);
    float scale = log1pf(expf(temp[h])) * logf(1024.0f);  // softplus * log(H*W)
    size_t o = (size_t)w * HD + lane;
    g_qs[o] = qn * scale;
    g_kn[o] = kn;
    g_v[o]  = v;
}

// ---------------- fused flash attention with SMEM rel-bias table --------------
// grid (16 row-tiles, H, B), 128 threads. 64 query rows per block.
// S phase:  thread grid 16x8, micro 4 rows x 8 cols
// O phase:  thread grid 16x8, micro 4 rows x 4 cols (D=32)
__global__ void attn_kernel(const int* __restrict__ rpi, float* __restrict__ out) {
    extern __shared__ float sm[];
    float* tab_s = sm;                      // 3972 (padded)
    float* q_s   = tab_s + 3972;            // [32][68]
    float* k_s   = q_s + 32 * 68;           // [32][68]
    float* v_s   = k_s + 32 * 68;           // [64][36]
    float* s_s   = v_s + 64 * 36;           // [64][68]

    const int n0 = blockIdx.x * 64;
    const int h  = blockIdx.y;
    const int b  = blockIdx.z;
    const int tid = threadIdx.x;
    const int tr = tid >> 3;   // 0..15
    const int tc = tid & 7;    // 0..7

    // load per-head bias table into SMEM
    for (int i = tid; i < TABLE_SZ; i += 128) tab_s[i] = g_tab[h * TABLE_SZ + i];
    // load q tile transposed: q_s[d][r]
    const float* qbase = g_qs + ((size_t)(b * NHEADS + h) * NN + n0) * HD;
#pragma unroll
    for (int i = 0; i < 16; i++) {
        int e = tid + i * 128;
        int r = e >> 5, d = e & 31;
        q_s[d * 68 + r] = qbase[e];
    }

    float O[4][4] = {};
    float mrow[4], lrow[4];
#pragma unroll
    for (int i = 0; i < 4; i++) { mrow[i] = -1e30f; lrow[i] = 0.f; }

    const float* kbase = g_kn + (size_t)(b * NHEADS + h) * NN * HD;
    const float* vbase = g_v  + (size_t)(b * NHEADS + h) * NN * HD;

    __syncthreads();

    for (int kt = 0; kt < 16; kt++) {
        const int m0 = kt * 64;
        __syncthreads();   // prev O-update done with v_s/s_s
        // cooperative load: k transposed, v natural
#pragma unroll
        for (int i = 0; i < 16; i++) {
            int e = tid + i * 128;
            int m = e >> 5, d = e & 31;
            float kv = kbase[(size_t)m0 * HD + e];
            float vv = vbase[(size_t)m0 * HD + e];
            k_s[d * 68 + m] = kv;
            v_s[m * 36 + d] = vv;
        }
        // bias gathers (independent of k_s)
        float acc[4][8];
#pragma unroll
        for (int i = 0; i < 4; i++) {
            const int* rp = rpi + (size_t)(n0 + tr * 4 + i) * NN + m0 + tc * 8;
            int4 ra = *reinterpret_cast<const int4*>(rp);
            int4 rb = *reinterpret_cast<const int4*>(rp + 4);
            acc[i][0] = tab_s[ra.x]; acc[i][1] = tab_s[ra.y];
            acc[i][2] = tab_s[ra.z]; acc[i][3] = tab_s[ra.w];
            acc[i][4] = tab_s[rb.x]; acc[i][5] = tab_s[rb.y];
            acc[i][6] = tab_s[rb.z]; acc[i][7] = tab_s[rb.w];
        }
        __syncthreads();   // k_s / v_s ready

        // S = q @ k^T + bias
#pragma unroll
        for (int d = 0; d < 32; d++) {
            float4 qv = *reinterpret_cast<float4*>(&q_s[d * 68 + tr * 4]);
            float4 ka = *reinterpret_cast<float4*>(&k_s[d * 68 + tc * 8]);
            float4 kb = *reinterpret_cast<float4*>(&k_s[d * 68 + tc * 8 + 4]);
            float qq[4] = {qv.x, qv.y, qv.z, qv.w};
            float kk[8] = {ka.x, ka.y, ka.z, ka.w, kb.x, kb.y, kb.z, kb.w};
#pragma unroll
            for (int i = 0; i < 4; i++)
#pragma unroll
                for (int j = 0; j < 8; j++) acc[i][j] += qq[i] * kk[j];
        }

        // online softmax (per row; 8 lanes share a row-group)
        float alpha_r[4];
#pragma unroll
        for (int i = 0; i < 4; i++) {
            float mx = acc[i][0];
#pragma unroll
            for (int j = 1; j < 8; j++) mx = fmaxf(mx, acc[i][j]);
#pragma unroll
            for (int o = 4; o; o >>= 1) mx = fmaxf(mx, __shfl_xor_sync(0xffffffffu, mx, o));
            float mnew = fmaxf(mrow[i], mx);
            alpha_r[i] = __expf(mrow[i] - mnew);
            float sum = 0.f;
#pragma unroll
            for (int j = 0; j < 8; j++) {
                float p = __expf(acc[i][j] - mnew);
                acc[i][j] = p;
                sum += p;
            }
#pragma unroll
            for (int o = 4; o; o >>= 1) sum += __shfl_xor_sync(0xffffffffu, sum, o);
            lrow[i] = lrow[i] * alpha_r[i] + sum;
            mrow[i] = mnew;
            float* sp = &s_s[(tr * 4 + i) * 68 + tc * 8];
            *reinterpret_cast<float4*>(sp)     = make_float4(acc[i][0], acc[i][1], acc[i][2], acc[i][3]);
            *reinterpret_cast<float4*>(sp + 4) = make_float4(acc[i][4], acc[i][5], acc[i][6], acc[i][7]);
        }
        __syncthreads();   // all p written

        // O = O*alpha + P @ V   (cols = tc*4 .. tc*4+3)
#pragma unroll
        for (int i = 0; i < 4; i++) {
            O[i][0] *= alpha_r[i]; O[i][1] *= alpha_r[i];
            O[i][2] *= alpha_r[i]; O[i][3] *= alpha_r[i];
        }
#pragma unroll 4
        for (int m4 = 0; m4 < 64; m4 += 4) {
            float4 vr0 = *reinterpret_cast<float4*>(&v_s[(m4 + 0) * 36 + tc * 4]);
            float4 vr1 = *reinterpret_cast<float4*>(&v_s[(m4 + 1) * 36 + tc * 4]);
            float4 vr2 = *reinterpret_cast<float4*>(&v_s[(m4 + 2) * 36 + tc * 4]);
            float4 vr3 = *reinterpret_cast<float4*>(&v_s[(m4 + 3) * 36 + tc * 4]);
#pragma unroll
            for (int i = 0; i < 4; i++) {
                float4 pv = *reinterpret_cast<float4*>(&s_s[(tr * 4 + i) * 68 + m4]);
                O[i][0] += pv.x * vr0.x + pv.y * vr1.x + pv.z * vr2.x + pv.w * vr3.x;
                O[i][1] += pv.x * vr0.y + pv.y * vr1.y + pv.z * vr2.y + pv.w * vr3.y;
                O[i][2] += pv.x * vr0.z + pv.y * vr1.z + pv.z * vr2.z + pv.w * vr3.z;
                O[i][3] += pv.x * vr0.w + pv.y * vr1.w + pv.z * vr2.w + pv.w * vr3.w;
            }
        }
    }

    // write O / l  -> g_ao[b][n][h*32 + d]
#pragma unroll
    for (int i = 0; i < 4; i++) {
        int n = n0 + tr * 4 + i;
        float inv = 1.f / lrow[i];
        float4 o4 = make_float4(O[i][0] * inv, O[i][1] * inv, O[i][2] * inv, O[i][3] * inv);
        *reinterpret_cast<float4*>(&out[((size_t)(b * NN + n)) * CDIM + h * HD + tc * 4]) = o4;
    }
}

// ---------------- launch ------------------------------------------------------
extern "C" void kernel_launch(void* const* d_in, const int* in_sizes, int n_in,
                              void* d_out, int out_size) {
    // input order (with optional scalar H, W at indices 1,2)
    int s = (n_in >= 15) ? 0 : -2;
    const float* x       = (const float*)d_in[0];
    const int*   rpi     = (const int*)  d_in[3 + s];
    const float* coords  = (const float*)d_in[4 + s];
    const float* qkv_w   = (const float*)d_in[5 + s];
    const float* qkv_b   = (const float*)d_in[6 + s];
    const float* qe      = (const float*)d_in[7 + s];
    const float* temp    = (const float*)d_in[8 + s];
    const float* proj_w  = (const float*)d_in[9 + s];
    const float* proj_b  = (const float*)d_in[10 + s];
    const float* fc1w    = (const float*)d_in[11 + s];
    const float* fc1b    = (const float*)d_in[12 + s];
    const float* fc2w    = (const float*)d_in[13 + s];
    const float* fc2b    = (const float*)d_in[14 + s];
    float* out = (float*)d_out;

    float *p_qkv, *p_ao;
    cudaGetSymbolAddress((void**)&p_qkv, g_qkv);
    cudaGetSymbolAddress((void**)&p_ao,  g_ao);

    // 1. CPB bias table
    cpb_kernel<<<TABLE_SZ, 128>>>(coords, fc1w, fc1b, fc2w, fc2b);

    // 2. qkv GEMM: [8192,256] @ [768,256]^T -> [8192,768]
    gemm_bias_kernel<<<dim3(768 / 64, (BB * NN) / 64), 256>>>(
        x, qkv_w, qkv_b, p_qkv, BB * NN, 3 * CDIM, CDIM);

    // 3. prep (l2norm, embeddings, scale, transpose to [b,h,n,d])
    {
        int warps = BB * NHEADS * NN;
        int threads = warps * 32;
        prep_kernel<<<(threads + 255) / 256, 256>>>(qe, temp);
    }

    // 4. fused attention
    {
        size_t smem = (3972 + 32 * 68 + 32 * 68 + 64 * 36 + 64 * 68) * sizeof(float);
        cudaFuncSetAttribute(attn_kernel, cudaFuncAttributeMaxDynamicSharedMemorySize, (int)smem);
        attn_kernel<<<dim3(16, NHEADS, BB), 128, smem>>>(rpi, p_ao);
    }

    // 5. proj GEMM: [8192,256] @ [256,256]^T -> out
    gemm_bias_kernel<<<dim3(CDIM / 64, (BB * NN) / 64), 256>>>(
        p_ao, proj_w, proj_b, out, BB * NN, CDIM, CDIM);
}

// round 2
// speedup vs baseline: 1.5390x; 1.5390x over previous
#include <cuda_runtime.h>
#include <math.h>
#include <stdint.h>

#define BB      8
#define NHEADS  8
#define HD      32
#define NN      1024
#define CDIM    256
#define TABLE_SZ 3969
#define CPBH    512

// ---------------- scratch ------------------------------------------------
__device__ float g_qkv[BB * NN * 3 * CDIM];
__device__ float g_qs [BB * NHEADS * NN * HD];
__device__ float g_kn [BB * NHEADS * NN * HD];
__device__ float g_v  [BB * NHEADS * NN * HD];
__device__ float g_tab[NHEADS * TABLE_SZ];
__device__ float g_ao [BB * NN * CDIM];

// ---------------- tf32 helpers -------------------------------------------
__device__ __forceinline__ void tf32x2(float x, uint32_t &hi, uint32_t &lo) {
    uint32_t h;
    asm("cvt.rna.tf32.f32 %0, %1;" : "=r"(h) : "f"(x));
    float rem = x - __uint_as_float(h);
    uint32_t l;
    asm("cvt.rna.tf32.f32 %0, %1;" : "=r"(l) : "f"(rem));
    hi = h; lo = l;
}

__device__ __forceinline__ void mma_tf32(float c[4],
                                         uint32_t a0, uint32_t a1, uint32_t a2, uint32_t a3,
                                         uint32_t b0, uint32_t b1) {
    asm volatile(
        "mma.sync.aligned.m16n8k8.row.col.f32.tf32.tf32.f32 "
        "{%0,%1,%2,%3}, {%4,%5,%6,%7}, {%8,%9}, {%0,%1,%2,%3};"
        : "+f"(c[0]), "+f"(c[1]), "+f"(c[2]), "+f"(c[3])
        : "r"(a0), "r"(a1), "r"(a2), "r"(a3), "r"(b0), "r"(b1));
}

// ---------------- CPB MLP -------------------------------------------------
__global__ void cpb_kernel(const float* __restrict__ coords,
                           const float* __restrict__ fc1w, const float* __restrict__ fc1b,
                           const float* __restrict__ fc2w, const float* __restrict__ fc2b) {
    int t = blockIdx.x;
    float c0 = coords[t * 2 + 0];
    float c1 = coords[t * 2 + 1];
    float acc[NHEADS];
#pragma unroll
    for (int h = 0; h < NHEADS; h++) acc[h] = 0.f;
    for (int j = threadIdx.x; j < CPBH; j += blockDim.x) {
        float hv = fmaxf(c0 * fc1w[j * 2] + c1 * fc1w[j * 2 + 1] + fc1b[j], 0.f);
#pragma unroll
        for (int h = 0; h < NHEADS; h++) acc[h] += hv * fc2w[h * CPBH + j];
    }
    __shared__ float red[4][NHEADS];
    int lane = threadIdx.x & 31, warp = threadIdx.x >> 5;
#pragma unroll
    for (int h = 0; h < NHEADS; h++)
        for (int o = 16; o; o >>= 1) acc[h] += __shfl_xor_sync(0xffffffffu, acc[h], o);
    if (lane == 0)
#pragma unroll
        for (int h = 0; h < NHEADS; h++) red[warp][h] = acc[h];
    __syncthreads();
    if (threadIdx.x < NHEADS) {
        float s = fc2b[threadIdx.x];
        for (int w = 0; w < 4; w++) s += red[w][threadIdx.x];
        g_tab[threadIdx.x * TABLE_SZ + t] = s;
    }
}

// ---------------- 3xTF32 GEMM: C[M][N] = A[M][K] @ W[N][K]^T + bias --------
// 128 threads, 4 warps 2x2, warp tile 32x32, BK=32
__global__ void __launch_bounds__(128) gemm_tc(const float* __restrict__ A,
                                               const float* __restrict__ W,
                                               const float* __restrict__ bias,
                                               float* __restrict__ C,
                                               int M, int N, int K) {
    __shared__ float As[64 * 36];
    __shared__ float Ws[64 * 36];
    const int bm = blockIdx.y * 64, bn = blockIdx.x * 64;
    const int tid = threadIdx.x, lane = tid & 31, warp = tid >> 5;
    const int wm = (warp >> 1) * 32, wn = (warp & 1) * 32;
    const int r = lane >> 2, c = lane & 3;

    float acc[2][4][4];
#pragma unroll
    for (int mt = 0; mt < 2; mt++)
#pragma unroll
        for (int nt = 0; nt < 4; nt++)
#pragma unroll
            for (int q = 0; q < 4; q++) acc[mt][nt][q] = 0.f;

    for (int k0 = 0; k0 < K; k0 += 32) {
#pragma unroll
        for (int i = 0; i < 4; i++) {
            int v = tid + i * 128;            // 0..511 float4 slots
            int row = v >> 3, kq = (v & 7) * 4;
            *(float4*)&As[row * 36 + kq] = *(const float4*)&A[(size_t)(bm + row) * K + k0 + kq];
            *(float4*)&Ws[row * 36 + kq] = *(const float4*)&W[(size_t)(bn + row) * K + k0 + kq];
        }
        __syncthreads();
#pragma unroll
        for (int kt = 0; kt < 4; kt++) {
            uint32_t ah[2][4], al[2][4];
#pragma unroll
            for (int mt = 0; mt < 2; mt++) {
                int rb = wm + mt * 16;
                tf32x2(As[(rb + r)     * 36 + kt * 8 + c],     ah[mt][0], al[mt][0]);
                tf32x2(As[(rb + r + 8) * 36 + kt * 8 + c],     ah[mt][1], al[mt][1]);
                tf32x2(As[(rb + r)     * 36 + kt * 8 + 4 + c], ah[mt][2], al[mt][2]);
                tf32x2(As[(rb + r + 8) * 36 + kt * 8 + 4 + c], ah[mt][3], al[mt][3]);
            }
#pragma unroll
            for (int nt = 0; nt < 4; nt++) {
                uint32_t bh0, bl0, bh1, bl1;
                tf32x2(Ws[(wn + nt * 8 + r) * 36 + kt * 8 + c],     bh0, bl0);
                tf32x2(Ws[(wn + nt * 8 + r) * 36 + kt * 8 + 4 + c], bh1, bl1);
#pragma unroll
                for (int mt = 0; mt < 2; mt++) {
                    mma_tf32(acc[mt][nt], ah[mt][0], ah[mt][1], ah[mt][2], ah[mt][3], bh0, bh1);
                    mma_tf32(acc[mt][nt], ah[mt][0], ah[mt][1], ah[mt][2], ah[mt][3], bl0, bl1);
                    mma_tf32(acc[mt][nt], al[mt][0], al[mt][1], al[mt][2], al[mt][3], bh0, bh1);
                }
            }
        }
        __syncthreads();
    }
#pragma unroll
    for (int mt = 0; mt < 2; mt++) {
        int row0 = bm + wm + mt * 16 + r;
        int row1 = row0 + 8;
#pragma unroll
        for (int nt = 0; nt < 4; nt++) {
            int n = bn + wn + nt * 8 + 2 * c;
            float b0 = bias[n], b1 = bias[n + 1];
            *(float2*)&C[(size_t)row0 * N + n] = make_float2(acc[mt][nt][0] + b0, acc[mt][nt][1] + b1);
            *(float2*)&C[(size_t)row1 * N + n] = make_float2(acc[mt][nt][2] + b0, acc[mt][nt][3] + b1);
        }
    }
}

// ---------------- prep ----------------------------------------------------
__global__ void prep_kernel(const float* __restrict__ qe, const float* __restrict__ temp) {
    int gtid = blockIdx.x * blockDim.x + threadIdx.x;
    int w = gtid >> 5;
    int lane = gtid & 31;
    if (w >= BB * NHEADS * NN) return;
    int n = w % NN;
    int h = (w / NN) % NHEADS;
    int b = w / (NN * NHEADS);
    size_t row = (size_t)(b * NN + n) * (3 * CDIM);
    float q = g_qkv[row + h * HD + lane];
    float k = g_qkv[row + CDIM + h * HD + lane];
    float v = g_qkv[row + 2 * CDIM + h * HD + lane];
    float q2 = q * q, k2 = k * k;
#pragma unroll
    for (int o = 16; o; o >>= 1) {
        q2 += __shfl_xor_sync(0xffffffffu, q2, o);
        k2 += __shfl_xor_sync(0xffffffffu, k2, o);
    }
    float qn = q / fmaxf(sqrtf(q2), 1e-12f) + qe[h * HD + lane];
    float kn = k / fmaxf(sqrtf(k2), 1e-12f);
    float scale = log1pf(expf(temp[h])) * logf(1024.0f);
    size_t o = (size_t)w * HD + lane;
    g_qs[o] = qn * scale;
    g_kn[o] = kn;
    g_v[o]  = v;
}

// ---------------- tensor-core flash attention ------------------------------
// grid (16, H, B), 128 threads (4 warps). Block: 64 q-rows, warp: 16 rows.
// S = (Q @ K^T + bias) via 3xTF32 mma; online softmax on fragments;
// P via SMEM; O += P @ V via 3xTF32 mma.
__global__ void __launch_bounds__(128) attn_tc(const int* __restrict__ rpi,
                                               float* __restrict__ out) {
    extern __shared__ float sm[];
    float* tab_s = sm;                         // 3972
    float* K_s   = tab_s + 3972;               // 64 x pitch 36
    float* V_s   = K_s + 64 * 36;              // 64 x pitch 40
    float* P_s   = V_s + 64 * 40;              // 64 x pitch 68 (also Q staging)

    const int n0 = blockIdx.x * 64;
    const int h  = blockIdx.y;
    const int b  = blockIdx.z;
    const int tid = threadIdx.x, lane = tid & 31, warp = tid >> 5;
    const int r = lane >> 2, c = lane & 3;

    for (int i = tid; i < TABLE_SZ; i += 128) tab_s[i] = g_tab[h * TABLE_SZ + i];

    // stage Q into P_s, build register-resident Q fragments (hi/lo)
    const float* qbase = g_qs + ((size_t)(b * NHEADS + h) * NN + n0) * HD;
#pragma unroll
    for (int i = 0; i < 16; i++) {
        int e = tid + i * 128;
        P_s[(e >> 5) * 68 + (e & 31)] = qbase[e];
    }
    __syncthreads();
    uint32_t qh[4][4], ql[4][4];
    {
        int rb = warp * 16;
#pragma unroll
        for (int ks = 0; ks < 4; ks++) {
            tf32x2(P_s[(rb + r)     * 68 + ks * 8 + c],     qh[ks][0], ql[ks][0]);
            tf32x2(P_s[(rb + r + 8) * 68 + ks * 8 + c],     qh[ks][1], ql[ks][1]);
            tf32x2(P_s[(rb + r)     * 68 + ks * 8 + 4 + c], qh[ks][2], ql[ks][2]);
            tf32x2(P_s[(rb + r + 8) * 68 + ks * 8 + 4 + c], qh[ks][3], ql[ks][3]);
        }
    }

    float O[4][4] = {};
    float ml0 = -1e30f, ml1 = -1e30f, ll0 = 0.f, ll1 = 0.f;
    const float* kbase = g_kn + (size_t)(b * NHEADS + h) * NN * HD;
    const float* vbase = g_v  + (size_t)(b * NHEADS + h) * NN * HD;
    const int*   rbase = rpi + (size_t)(n0 + warp * 16) * NN;

    for (int kt = 0; kt < 16; kt++) {
        __syncthreads();    // prior PV reads of K_s/V_s and Q-frag reads of P_s done
#pragma unroll
        for (int i = 0; i < 16; i++) {
            int e = tid + i * 128;
            int m = e >> 5, d = e & 31;
            float kv = kbase[kt * 2048 + e];
            float vv = vbase[kt * 2048 + e];
            K_s[m * 36 + d] = kv;
            V_s[m * 40 + d] = vv;
        }
        __syncthreads();

        // ---- S = Q K^T + bias ----
        float sc[8][4];
#pragma unroll
        for (int j = 0; j < 8; j++) {
            int colb = kt * 64 + j * 8 + 2 * c;
            int2 ia = *(const int2*)&rbase[(size_t)r       * NN + colb];
            int2 ib = *(const int2*)&rbase[(size_t)(r + 8) * NN + colb];
            sc[j][0] = tab_s[ia.x]; sc[j][1] = tab_s[ia.y];
            sc[j][2] = tab_s[ib.x]; sc[j][3] = tab_s[ib.y];
#pragma unroll
            for (int ks = 0; ks < 4; ks++) {
                uint32_t bh0, bl0, bh1, bl1;
                tf32x2(K_s[(j * 8 + r) * 36 + ks * 8 + c],     bh0, bl0);
                tf32x2(K_s[(j * 8 + r) * 36 + ks * 8 + 4 + c], bh1, bl1);
                mma_tf32(sc[j], qh[ks][0], qh[ks][1], qh[ks][2], qh[ks][3], bh0, bh1);
                mma_tf32(sc[j], qh[ks][0], qh[ks][1], qh[ks][2], qh[ks][3], bl0, bl1);
                mma_tf32(sc[j], ql[ks][0], ql[ks][1], ql[ks][2], ql[ks][3], bh0, bh1);
            }
        }

        // ---- online softmax (thread owns 2 rows: r and r+8 of warp tile) ----
        float mx0 = -1e30f, mx1 = -1e30f;
#pragma unroll
        for (int j = 0; j < 8; j++) {
            mx0 = fmaxf(mx0, fmaxf(sc[j][0], sc[j][1]));
            mx1 = fmaxf(mx1, fmaxf(sc[j][2], sc[j][3]));
        }
        mx0 = fmaxf(mx0, __shfl_xor_sync(0xffffffffu, mx0, 1));
        mx0 = fmaxf(mx0, __shfl_xor_sync(0xffffffffu, mx0, 2));
        mx1 = fmaxf(mx1, __shfl_xor_sync(0xffffffffu, mx1, 1));
        mx1 = fmaxf(mx1, __shfl_xor_sync(0xffffffffu, mx1, 2));
        float mn0 = fmaxf(ml0, mx0), mn1 = fmaxf(ml1, mx1);
        float a0 = __expf(ml0 - mn0), a1 = __expf(ml1 - mn1);
        float s0 = 0.f, s1 = 0.f;
        float* prow0 = &P_s[(warp * 16 + r)     * 68];
        float* prow1 = &P_s[(warp * 16 + r + 8) * 68];
#pragma unroll
        for (int j = 0; j < 8; j++) {
            float p0 = __expf(sc[j][0] - mn0), p1 = __expf(sc[j][1] - mn0);
            float p2 = __expf(sc[j][2] - mn1), p3 = __expf(sc[j][3] - mn1);
            s0 += p0 + p1; s1 += p2 + p3;
            *(float2*)&prow0[j * 8 + 2 * c] = make_float2(p0, p1);
            *(float2*)&prow1[j * 8 + 2 * c] = make_float2(p2, p3);
        }
        s0 += __shfl_xor_sync(0xffffffffu, s0, 1);
        s0 += __shfl_xor_sync(0xffffffffu, s0, 2);
        s1 += __shfl_xor_sync(0xffffffffu, s1, 1);
        s1 += __shfl_xor_sync(0xffffffffu, s1, 2);
        ll0 = ll0 * a0 + s0; ll1 = ll1 * a1 + s1;
        ml0 = mn0; ml1 = mn1;
#pragma unroll
        for (int jd = 0; jd < 4; jd++) {
            O[jd][0] *= a0; O[jd][1] *= a0;
            O[jd][2] *= a1; O[jd][3] *= a1;
        }
        __syncwarp();   // P_s rows are warp-private; order stores vs loads

        // ---- O += P @ V ----
#pragma unroll
        for (int kk = 0; kk < 8; kk++) {
            uint32_t ah[4], al[4];
            tf32x2(P_s[(warp * 16 + r)     * 68 + kk * 8 + c],     ah[0], al[0]);
            tf32x2(P_s[(warp * 16 + r + 8) * 68 + kk * 8 + c],     ah[1], al[1]);
            tf32x2(P_s[(warp * 16 + r)     * 68 + kk * 8 + 4 + c], ah[2], al[2]);
            tf32x2(P_s[(warp * 16 + r + 8) * 68 + kk * 8 + 4 + c], ah[3], al[3]);
#pragma unroll
            for (int jd = 0; jd < 4; jd++) {
                uint32_t vh0, vl0, vh1, vl1;
                tf32x2(V_s[(kk * 8 + c)     * 40 + jd * 8 + r], vh0, vl0);
                tf32x2(V_s[(kk * 8 + 4 + c) * 40 + jd * 8 + r], vh1, vl1);
                mma_tf32(O[jd], ah[0], ah[1], ah[2], ah[3], vh0, vh1);
                mma_tf32(O[jd], ah[0], ah[1], ah[2], ah[3], vl0, vl1);
                mma_tf32(O[jd], al[0], al[1], al[2], al[3], vh0, vh1);
            }
        }
    }

    // ---- epilogue: normalize + write [b][n][h*32+d] ----
    float i0 = 1.f / ll0, i1 = 1.f / ll1;
    int row0 = n0 + warp * 16 + r;
    int row1 = row0 + 8;
#pragma unroll
    for (int jd = 0; jd < 4; jd++) {
        int col = h * HD + jd * 8 + 2 * c;
        *(float2*)&out[(size_t)(b * NN + row0) * CDIM + col] =
            make_float2(O[jd][0] * i0, O[jd][1] * i0);
        *(float2*)&out[(size_t)(b * NN + row1) * CDIM + col] =
            make_float2(O[jd][2] * i1, O[jd][3] * i1);
    }
}

// ---------------- launch ----------------------------------------------------
extern "C" void kernel_launch(void* const* d_in, const int* in_sizes, int n_in,
                              void* d_out, int out_size) {
    int s = (n_in >= 15) ? 0 : -2;
    const float* x       = (const float*)d_in[0];
    const int*   rpi     = (const int*)  d_in[3 + s];
    const float* coords  = (const float*)d_in[4 + s];
    const float* qkv_w   = (const float*)d_in[5 + s];
    const float* qkv_b   = (const float*)d_in[6 + s];
    const float* qe      = (const float*)d_in[7 + s];
    const float* temp    = (const float*)d_in[8 + s];
    const float* proj_w  = (const float*)d_in[9 + s];
    const float* proj_b  = (const float*)d_in[10 + s];
    const float* fc1w    = (const float*)d_in[11 + s];
    const float* fc1b    = (const float*)d_in[12 + s];
    const float* fc2w    = (const float*)d_in[13 + s];
    const float* fc2b    = (const float*)d_in[14 + s];
    float* out = (float*)d_out;

    float *p_qkv, *p_ao;
    cudaGetSymbolAddress((void**)&p_qkv, g_qkv);
    cudaGetSymbolAddress((void**)&p_ao,  g_ao);

    cpb_kernel<<<TABLE_SZ, 128>>>(coords, fc1w, fc1b, fc2w, fc2b);

    gemm_tc<<<dim3(768 / 64, (BB * NN) / 64), 128>>>(
        x, qkv_w, qkv_b, p_qkv, BB * NN, 3 * CDIM, CDIM);

    {
        int warps = BB * NHEADS * NN;
        int threads = warps * 32;
        prep_kernel<<<(threads + 255) / 256, 256>>>(qe, temp);
    }

    {
        size_t smem = (3972 + 64 * 36 + 64 * 40 + 64 * 68) * sizeof(float);
        cudaFuncSetAttribute(attn_tc, cudaFuncAttributeMaxDynamicSharedMemorySize, (int)smem);
        attn_tc<<<dim3(16, NHEADS, BB), 128, smem>>>(rpi, p_ao);
    }

    gemm_tc<<<dim3(CDIM / 64, (BB * NN) / 64), 128>>>(
        p_ao, proj_w, proj_b, out, BB * NN, CDIM, CDIM);
}